// round 15
// baseline (speedup 1.0000x reference)
#include <cuda_runtime.h>
#include <cuda_bf16.h>
#include <math.h>
#include <stdint.h>

// Problem constants
#define NB   2
#define LEN  2048
#define EMB  1024
#define NH   16
#define HX   64          // head dim
#define TEMPINV 0.125f   // 1/sqrt(EMB/HEADS) = 1/8
#define XN   ((size_t)NB * LEN * EMB)   // 4194304
#define WN   ((size_t)EMB * EMB)        // 1048576

// ---------------- device scratch ---------------------------------------------
__device__ float g_Qp[(size_t)NB * NH * LEN * HX];   // (b,h,q,x) tf32-rounded
__device__ float g_Kp[(size_t)NB * NH * LEN * HX];   // (b,h,k,x) tf32-rounded
__device__ float g_Vp[(size_t)NB * NH * HX * LEN];   // (b,h,x,k) TRANSPOSED, tf32-rounded
__device__ float g_AO[(size_t)NB * LEN * EMB];       // (b,q,e) tf32-rounded
__device__ float g_P [(size_t)NB * NH * LEN * LEN];  // (b,h,q,k) unnormalized E
__device__ float g_L [(size_t)NB * NH * LEN];        // 1/rowsum per (b,h,q)
// pre-rounded inputs
__device__ float g_Qr[XN];
__device__ float g_Kr[XN];
__device__ float g_Vr[XN];
__device__ float g_Wq[WN];
__device__ float g_Wk[WN];
__device__ float g_Wv[WN];
__device__ float g_Wo[WN];

// ---------------- helpers ----------------------------------------------------
__device__ __forceinline__ uint32_t f2tf(float x) {
    uint32_t u;
    asm("cvt.rna.tf32.f32 %0, %1;" : "=r"(u) : "f"(x));
    return u;
}
__device__ __forceinline__ float f2tff(float x) { return __uint_as_float(f2tf(x)); }
__device__ __forceinline__ void mma8(float* d, const uint32_t* a, const uint32_t* b) {
    asm("mma.sync.aligned.m16n8k8.row.col.f32.tf32.tf32.f32 "
        "{%0,%1,%2,%3},{%4,%5,%6,%7},{%8,%9},{%0,%1,%2,%3};"
        : "+f"(d[0]), "+f"(d[1]), "+f"(d[2]), "+f"(d[3])
        : "r"(a[0]), "r"(a[1]), "r"(a[2]), "r"(a[3]), "r"(b[0]), "r"(b[1]));
}
__device__ __forceinline__ void cp16(float* dst, const float* src) {
    uint32_t d = (uint32_t)__cvta_generic_to_shared(dst);
    asm volatile("cp.async.cg.shared.global [%0], [%1], 16;" :: "r"(d), "l"(src));
}
#define CP_COMMIT asm volatile("cp.async.commit_group;")
#define CP_WAIT0  asm volatile("cp.async.wait_group 0;")
#define CP_WAIT1  asm volatile("cp.async.wait_group 1;")
#define LU(p)  __float_as_uint(p)
#define LDSM4(R, addr) \
    asm volatile("ldmatrix.sync.aligned.m8n8.x4.shared.b16 {%0,%1,%2,%3}, [%4];" \
        : "=r"((R)[0]), "=r"((R)[1]), "=r"((R)[2]), "=r"((R)[3]) : "r"(addr))

// ---------------- round inputs to tf32 once ----------------------------------
__global__ __launch_bounds__(256) void round_kernel(
    const float* __restrict__ q, const float* __restrict__ k,
    const float* __restrict__ v,
    const float* __restrict__ Wq, const float* __restrict__ Wk,
    const float* __restrict__ Wv, const float* __restrict__ Wo)
{
    const float* src; float* dst; size_t n;
    switch (blockIdx.z) {
        case 0: src = q;  dst = g_Qr; n = XN; break;
        case 1: src = k;  dst = g_Kr; n = XN; break;
        case 2: src = v;  dst = g_Vr; n = XN; break;
        case 3: src = Wq; dst = g_Wq; n = WN; break;
        case 4: src = Wk; dst = g_Wk; n = WN; break;
        case 5: src = Wv; dst = g_Wv; n = WN; break;
        default: src = Wo; dst = g_Wo; n = WN; break;
    }
    size_t stride = (size_t)gridDim.x * blockDim.x;
    for (size_t i = (size_t)blockIdx.x * blockDim.x + threadIdx.x; i < n / 4; i += stride) {
        float4 t = ((const float4*)src)[i];
        t.x = f2tff(t.x); t.y = f2tff(t.y); t.z = f2tff(t.z); t.w = f2tff(t.w);
        ((float4*)dst)[i] = t;
    }
}

// ---------------- GEMM core (tf32 mma, 128x128 block, 2-stage pipeline) ------
#define GA  (128 * 36)
#define GB  (32 * 132)
#define GEMM_SMEM (2 * (GA + GB) * 4)   // 70656 B -> 2 CTAs/SM

__device__ __forceinline__ void gemm_copy_tile(
    float* As, float* Bs, const float* X, const float* W,
    int row0, int n0, int k0, int tid)
{
    #pragma unroll
    for (int p = 0; p < 4; p++) {
        int idx = p * 256 + tid;
        int m = idx >> 3, kf = idx & 7;
        cp16(&As[m * 36 + 4 * kf], &X[(size_t)(row0 + m) * 1024 + k0 + 4 * kf]);
    }
    #pragma unroll
    for (int p = 0; p < 4; p++) {
        int idx = p * 256 + tid;
        int kk = idx >> 5, nf = idx & 31;
        cp16(&Bs[kk * 132 + 4 * nf], &W[(size_t)(k0 + kk) * 1024 + n0 + 4 * nf]);
    }
    CP_COMMIT;
}

__device__ __forceinline__ void gemm_core(
    const float* X, const float* W, float d[2][8][4],
    int row0, int n0, int tid, float* smx)
{
    float* As0 = smx;
    float* As1 = smx + GA;
    float* Bs0 = smx + 2 * GA;
    float* Bs1 = smx + 2 * GA + GB;

    int lane = tid & 31, wrp = tid >> 5;
    int lr = lane >> 2, lc = lane & 3;
    int mw = (wrp & 3) * 32;        // 4 warps along M
    int nw = (wrp >> 2) * 64;       // 2 warps along N (64 each)

    gemm_copy_tile(As0, Bs0, X, W, row0, n0, 0, tid);

    #pragma unroll 1
    for (int t = 0; t < 32; t++) {
        float* As  = (t & 1) ? As1 : As0;
        float* Bs  = (t & 1) ? Bs1 : Bs0;
        float* Asn = (t & 1) ? As0 : As1;
        float* Bsn = (t & 1) ? Bs0 : Bs1;
        CP_WAIT0;
        __syncthreads();
        if (t < 31) gemm_copy_tile(Asn, Bsn, X, W, row0, n0, (t + 1) * 32, tid);

        #pragma unroll
        for (int ks = 0; ks < 4; ks++) {
            uint32_t a[2][4];
            #pragma unroll
            for (int mt = 0; mt < 2; mt++) {
                int rb = mw + mt * 16 + lr;
                a[mt][0] = LU(As[(rb    ) * 36 + ks * 8 + lc    ]);
                a[mt][1] = LU(As[(rb + 8) * 36 + ks * 8 + lc    ]);
                a[mt][2] = LU(As[(rb    ) * 36 + ks * 8 + lc + 4]);
                a[mt][3] = LU(As[(rb + 8) * 36 + ks * 8 + lc + 4]);
            }
            #pragma unroll
            for (int nt = 0; nt < 8; nt++) {
                uint32_t b[2];
                int cb = nw + nt * 8 + lr;
                b[0] = LU(Bs[(ks * 8 + lc    ) * 132 + cb]);
                b[1] = LU(Bs[(ks * 8 + lc + 4) * 132 + cb]);
                mma8(d[0][nt], a[0], b);
                mma8(d[1][nt], a[1], b);
            }
        }
    }
}

// ---------------- projection kernel ------------------------------------------
__global__ __launch_bounds__(256, 2) void proj_kernel(
    const float* __restrict__ bq, const float* __restrict__ bk,
    const float* __restrict__ bv)
{
    extern __shared__ float smx[];
    const float* X; const float* W; const float* bias; float* out;
    int z = blockIdx.z;
    if (z == 0)      { X = g_Qr; W = g_Wq; bias = bq; out = g_Qp; }
    else if (z == 1) { X = g_Kr; W = g_Wk; bias = bk; out = g_Kp; }
    else             { X = g_Vr; W = g_Wv; bias = bv; out = g_Vp; }
    bool vtrans = (z == 2);

    int tid = threadIdx.x;
    int lane = tid & 31, wrp = tid >> 5;
    int lr = lane >> 2, lc = lane & 3;
    int mw = (wrp & 3) * 32, nw = (wrp >> 2) * 64;
    int row0 = blockIdx.y * 128;
    int n0   = blockIdx.x * 128;

    float d[2][8][4];
    #pragma unroll
    for (int mt = 0; mt < 2; mt++)
        #pragma unroll
        for (int nt = 0; nt < 8; nt++)
            #pragma unroll
            for (int r = 0; r < 4; r++) d[mt][nt][r] = 0.f;

    gemm_core(X, W, d, row0, n0, tid, smx);

    // epilogue: head-major scatter, tf32-rounded. e = x*16 + h
    #pragma unroll
    for (int mt = 0; mt < 2; mt++)
        #pragma unroll
        for (int nt = 0; nt < 8; nt++)
            #pragma unroll
            for (int r = 0; r < 4; r++) {
                int row = row0 + mw + mt * 16 + lr + ((r >= 2) ? 8 : 0);
                int e = n0 + nw + nt * 8 + 2 * lc + (r & 1);
                int b = row >> 11, l = row & 2047;
                int hh = e & 15, x = e >> 4;
                float v = f2tff(d[mt][nt][r] + bias[e]);
                if (vtrans)
                    out[(((size_t)(b * 16 + hh) * HX) + x) * LEN + l] = v;
                else
                    out[(((size_t)(b * 16 + hh) * LEN) + l) * HX + x] = v;
            }
}

// ---------------- attention kernel (double-K, 5 buffers, 2 CTAs/SM) ----------
// Qs[q][x], Ks0/Ks1[k][x], Vs[x][k], Ss[q][k] raw E (HMMA truncates to tf32).
#define SST 68
#define ATT (64 * SST)
#define ATT_SMEM (5 * ATT * 4)   // 87040 B -> 2 CTAs/SM

__global__ __launch_bounds__(256, 2) void attn_kernel(const unsigned char* __restrict__ mask)
{
    extern __shared__ float sm[];
    float* Qs  = sm;               // [q][x]
    float* Ks0 = sm + ATT;         // [k][x]
    float* Ks1 = sm + 2 * ATT;
    float* Vs  = sm + 3 * ATT;     // [x][k]
    float* Ss  = sm + 4 * ATT;     // [q][k] raw E
    __shared__ float lrow[64];

    int tid = threadIdx.x;
    int lane = tid & 31, wrp = tid >> 5;
    int lr = lane >> 2, lc = lane & 3;
    int kw = (wrp >> 1) * 16;      // warp k-rows (QK) / x-rows (PV)
    int qw = (wrp & 1) * 32;       // warp q-cols
    int q0 = blockIdx.x * 64;
    int h  = blockIdx.y;
    int b  = blockIdx.z;
    size_t bh = (size_t)(b * 16 + h);

    const float* Qbase = g_Qp + bh * LEN * HX + (size_t)q0 * HX;
    const float* Kb    = g_Kp + bh * LEN * HX;
    const float* VbT   = g_Vp + bh * HX * LEN;          // [x][k]
    float*       Pb    = g_P  + bh * LEN * LEN + (size_t)q0 * LEN;
    const unsigned char* maskb = mask + b * LEN;

    // ldmatrix per-thread base addresses (bytes)
    uint32_t qs_u = (uint32_t)__cvta_generic_to_shared(Qs);
    uint32_t k0_u = (uint32_t)__cvta_generic_to_shared(Ks0);
    uint32_t k1_u = (uint32_t)__cvta_generic_to_shared(Ks1);
    uint32_t vs_u = (uint32_t)__cvta_generic_to_shared(Vs);
    uint32_t ss_u = (uint32_t)__cvta_generic_to_shared(Ss);
    uint32_t aoff = 4u * ((kw + (lane & 15)) * SST + (lane >> 4) * 4);
    uint32_t ksB0 = k0_u + aoff;
    uint32_t ksB1 = k1_u + aoff;
    uint32_t vsB  = vs_u + aoff;
    uint32_t boff = 4u * ((qw + (lane & 7) + (lane >> 4) * 8) * SST + ((lane >> 3) & 1) * 4);
    uint32_t qsB0 = qs_u + boff;
    uint32_t qsB1 = qsB0 + 4u * 16 * SST;
    uint32_t ssB0 = ss_u + boff;
    uint32_t ssB1 = ssB0 + 4u * 16 * SST;

    // P-write pointers (advance 64 floats/tile)
    const float* srcp = Ss + (tid >> 2) * SST + (tid & 3) * 16;
    float*       dstp = Pb + (size_t)(tid >> 2) * LEN + (tid & 3) * 16;

    // prologue: async-copy Q tile + K tile 0 (one group)
    #pragma unroll
    for (int p = 0; p < 4; p++) {
        int idx = p * 256 + tid;
        int r = idx >> 4, f = idx & 15;
        cp16(&Qs[r * SST + 4 * f], &Qbase[idx * 4]);
        cp16(&Ks0[r * SST + 4 * f], &Kb[idx * 4]);
    }
    CP_COMMIT;
    if (tid < 64) lrow[tid] = 0.f;

    float ofr[4][4];
    float cs[4][2];
    #pragma unroll
    for (int nt = 0; nt < 4; nt++) {
        cs[nt][0] = 0.f; cs[nt][1] = 0.f;
        #pragma unroll
        for (int r = 0; r < 4; r++) ofr[nt][r] = 0.f;
    }

    #pragma unroll 1
    for (int kt = 0; kt < 32; kt++) {
        int k0 = kt * 64;
        uint32_t ksB = (kt & 1) ? ksB1 : ksB0;
        float* Ksn   = (kt & 1) ? Ks0 : Ks1;
        CP_WAIT0;            // K(kt) (and Q on kt=0) ready
        __syncthreads();     // PV(kt-1) done -> Vs/Ss reusable

        // issue V(kt) copy (own group), then K(kt+1)
        #pragma unroll
        for (int p = 0; p < 4; p++) {
            int idx = p * 256 + tid;
            int x = idx >> 4, f = idx & 15;
            cp16(&Vs[x * SST + 4 * f], &VbT[(size_t)x * LEN + k0 + 4 * f]);
        }
        CP_COMMIT;
        if (kt < 31) {
            #pragma unroll
            for (int p = 0; p < 4; p++) {
                int idx = p * 256 + tid;
                int r = idx >> 4, f = idx & 15;
                cp16(&Ksn[r * SST + 4 * f], &Kb[(size_t)(k0 + 64) * HX + idx * 4]);
            }
            CP_COMMIT;
        }

        float mk_lo = (float)maskb[k0 + kw + lr];
        float mk_hi = (float)maskb[k0 + kw + lr + 8];

        // S^T = K @ Q^T via ldmatrix fragments
        float sfr[4][4];
        #pragma unroll
        for (int nt = 0; nt < 4; nt++)
            #pragma unroll
            for (int r = 0; r < 4; r++) sfr[nt][r] = 0.f;
        #pragma unroll
        for (int xs = 0; xs < 8; xs++) {
            uint32_t aK[4], b01[4], b23[4];
            LDSM4(aK, ksB + xs * 32);
            LDSM4(b01, qsB0 + xs * 32);
            LDSM4(b23, qsB1 + xs * 32);
            mma8(sfr[0], aK, b01);
            mma8(sfr[1], aK, b01 + 2);
            mma8(sfr[2], aK, b23);
            mma8(sfr[3], aK, b23 + 2);
        }

        // E = exp(S/T) (masked -> 0); csum in regs; raw E -> Ss[q][k]
        #pragma unroll
        for (int nt = 0; nt < 4; nt++) {
            int qb = qw + nt * 8 + 2 * lc;
            float e00 = (mk_lo != 0.f) ? 0.f : __expf(sfr[nt][0] * TEMPINV);
            float e01 = (mk_lo != 0.f) ? 0.f : __expf(sfr[nt][1] * TEMPINV);
            float e10 = (mk_hi != 0.f) ? 0.f : __expf(sfr[nt][2] * TEMPINV);
            float e11 = (mk_hi != 0.f) ? 0.f : __expf(sfr[nt][3] * TEMPINV);
            cs[nt][0] += e00 + e10;
            cs[nt][1] += e01 + e11;
            Ss[(qb    ) * SST + kw + lr    ] = e00;
            Ss[(qb    ) * SST + kw + lr + 8] = e10;
            Ss[(qb + 1) * SST + kw + lr    ] = e01;
            Ss[(qb + 1) * SST + kw + lr + 8] = e11;
        }
        // V(kt) must be resident before PV; K(kt+1) may still be in flight
        if (kt < 31) { CP_WAIT1; } else { CP_WAIT0; }
        __syncthreads();

        // P tile write: coalesced float4 rows from Ss
        {
            float4* dp = (float4*)dstp;
            dp[0] = ((const float4*)srcp)[0];
            dp[1] = ((const float4*)srcp)[1];
            dp[2] = ((const float4*)srcp)[2];
            dp[3] = ((const float4*)srcp)[3];
            dstp += 64;
        }

        // PV: O^T += V^T @ E^T via ldmatrix (E truncated to tf32 by HMMA)
        #pragma unroll
        for (int ks = 0; ks < 8; ks++) {
            uint32_t aV[4], b01[4], b23[4];
            LDSM4(aV, vsB + ks * 32);
            LDSM4(b01, ssB0 + ks * 32);
            LDSM4(b23, ssB1 + ks * 32);
            mma8(ofr[0], aV, b01);
            mma8(ofr[1], aV, b01 + 2);
            mma8(ofr[2], aV, b23);
            mma8(ofr[3], aV, b23 + 2);
        }
    }

    // reduce csum: over lr (shfl), then across warps (shared atomics)
    #pragma unroll
    for (int nt = 0; nt < 4; nt++)
        #pragma unroll
        for (int j = 0; j < 2; j++) {
            float s = cs[nt][j];
            s += __shfl_xor_sync(0xffffffffu, s, 4);
            s += __shfl_xor_sync(0xffffffffu, s, 8);
            s += __shfl_xor_sync(0xffffffffu, s, 16);
            if (lane < 4) atomicAdd(&lrow[qw + nt * 8 + 2 * lc + j], s);
        }
    __syncthreads();
    if (tid < 64) {
        float inv = 1.f / lrow[tid];
        lrow[tid] = inv;
        g_L[bh * LEN + q0 + tid] = inv;
    }
    __syncthreads();

    // write O scaled by 1/l, tf32-rounded (outproj consumes without CVT)
    int xw = kw;
    #pragma unroll
    for (int nt = 0; nt < 4; nt++) {
        int ql = qw + nt * 8 + 2 * lc;
        int qg = q0 + ql;
        int x0 = xw + lr;
        float l0 = lrow[ql], l1 = lrow[ql + 1];
        g_AO[((size_t)b * LEN + qg    ) * EMB + x0 * 16 + h]       = f2tff(ofr[nt][0] * l0);
        g_AO[((size_t)b * LEN + qg + 1) * EMB + x0 * 16 + h]       = f2tff(ofr[nt][1] * l1);
        g_AO[((size_t)b * LEN + qg    ) * EMB + (x0 + 8) * 16 + h] = f2tff(ofr[nt][2] * l0);
        g_AO[((size_t)b * LEN + qg + 1) * EMB + (x0 + 8) * 16 + h] = f2tff(ofr[nt][3] * l1);
    }
}

// ---------------- tail kernel: outproj CTAs + transpose CTAs merged ----------
// blockIdx.x < 256  -> outproj tile (scheduled first, hides inside transpose)
// blockIdx.x >= 256 -> transpose+normalize tile
#define TAIL_OUT_CTAS 256

__global__ __launch_bounds__(256, 2) void tail_kernel(
    const float* __restrict__ bo, float* __restrict__ out)
{
    extern __shared__ float smx[];
    int bx = blockIdx.x;
    int tid = threadIdx.x;

    if (bx < TAIL_OUT_CTAS) {
        // ---- outproj: attn_o = AO @ Wo + bo ----
        int lane = tid & 31, wrp = tid >> 5;
        int lr = lane >> 2, lc = lane & 3;
        int mw = (wrp & 3) * 32, nw = (wrp >> 2) * 64;
        int row0 = (bx >> 3) * 128;
        int n0   = (bx & 7) * 128;

        float d[2][8][4];
        #pragma unroll
        for (int mt = 0; mt < 2; mt++)
            #pragma unroll
            for (int nt = 0; nt < 8; nt++)
                #pragma unroll
                for (int r = 0; r < 4; r++) d[mt][nt][r] = 0.f;

        gemm_core(g_AO, g_Wo, d, row0, n0, tid, smx);

        #pragma unroll
        for (int mt = 0; mt < 2; mt++)
            #pragma unroll
            for (int nt = 0; nt < 8; nt++)
                #pragma unroll
                for (int r = 0; r < 4; r++) {
                    size_t row = row0 + mw + mt * 16 + lr + ((r >= 2) ? 8 : 0);
                    int e = n0 + nw + nt * 8 + 2 * lc + (r & 1);
                    out[row * 1024 + e] = d[mt][nt][r] + bo[e];
                }
    } else {
        // ---- transpose+normalize: (b,h,q,k) E -> (b,q,k,h) P ----
        __shared__ float linv16[16];
        float* tile = smx;   // 16*257 floats = 16448 <= dynamic smem
        int t = bx - TAIL_OUT_CTAS;
        int k0 = (t & 7) * 256;
        int q  = (t >> 3) & 2047;
        int b  = t >> 14;
        float* out2 = out + (size_t)NB * LEN * EMB;

        if (tid < 16) linv16[tid] = g_L[((size_t)(b * 16 + tid)) * LEN + q];

        const float* src = g_P + ((size_t)(b * 16) * LEN + q) * LEN + k0;
        #pragma unroll
        for (int hh = 0; hh < 16; hh++)
            tile[hh * 257 + tid] = src[(size_t)hh * LEN * LEN + tid];
        __syncthreads();

        float* dst = out2 + ((size_t)(b * LEN + q) * LEN + k0 + tid) * 16;
        #pragma unroll
        for (int g = 0; g < 4; g++) {
            float4 v;
            v.x = tile[(4 * g + 0) * 257 + tid] * linv16[4 * g + 0];
            v.y = tile[(4 * g + 1) * 257 + tid] * linv16[4 * g + 1];
            v.z = tile[(4 * g + 2) * 257 + tid] * linv16[4 * g + 2];
            v.w = tile[(4 * g + 3) * 257 + tid] * linv16[4 * g + 3];
            *(float4*)&dst[4 * g] = v;
        }
    }
}

// ---------------- launch -----------------------------------------------------
extern "C" void kernel_launch(void* const* d_in, const int* in_sizes, int n_in,
                              void* d_out, int out_size)
{
    const float* query = (const float*)d_in[0];
    const float* key   = (const float*)d_in[1];
    const float* value = (const float*)d_in[2];
    const unsigned char* mask = (const unsigned char*)d_in[3];
    const float* bq = (const float*)d_in[5];
    const float* bk = (const float*)d_in[7];
    const float* bv = (const float*)d_in[9];
    const float* bo = (const float*)d_in[11];
    const float* Wq = (const float*)d_in[4];
    const float* Wk = (const float*)d_in[6];
    const float* Wv = (const float*)d_in[8];
    const float* Wo = (const float*)d_in[10];
    float* out = (float*)d_out;

    cudaFuncSetAttribute(attn_kernel, cudaFuncAttributeMaxDynamicSharedMemorySize, ATT_SMEM);
    cudaFuncSetAttribute(proj_kernel, cudaFuncAttributeMaxDynamicSharedMemorySize, GEMM_SMEM);
    cudaFuncSetAttribute(tail_kernel, cudaFuncAttributeMaxDynamicSharedMemorySize, GEMM_SMEM);

    round_kernel<<<dim3(192, 1, 7), 256>>>(query, key, value, Wq, Wk, Wv, Wo);
    proj_kernel<<<dim3(8, 32, 3), 256, GEMM_SMEM>>>(bq, bk, bv);
    attn_kernel<<<dim3(LEN / 64, NH, NB), 256, ATT_SMEM>>>(mask);
    tail_kernel<<<dim3(TAIL_OUT_CTAS + (LEN / 256) * LEN * NB, 1, 1), 256, GEMM_SMEM>>>(bo, out);
}

// round 16
// speedup vs baseline: 1.1959x; 1.1959x over previous
#include <cuda_runtime.h>
#include <cuda_bf16.h>
#include <math.h>
#include <stdint.h>

// Problem constants
#define NB   2
#define LEN  2048
#define EMB  1024
#define NH   16
#define HX   64          // head dim
#define TEMPINV 0.125f   // 1/sqrt(EMB/HEADS) = 1/8
#define XN   ((size_t)NB * LEN * EMB)   // 4194304
#define WN   ((size_t)EMB * EMB)        // 1048576

// ---------------- device scratch ---------------------------------------------
__device__ float g_Qp[(size_t)NB * NH * LEN * HX];   // (b,h,q,x) tf32-rounded
__device__ float g_Kp[(size_t)NB * NH * LEN * HX];   // (b,h,k,x) tf32-rounded
__device__ float g_Vp[(size_t)NB * NH * HX * LEN];   // (b,h,x,k) TRANSPOSED, tf32-rounded
__device__ float g_AO[(size_t)NB * LEN * EMB];       // (b,q,e) tf32-rounded
__device__ float g_P [(size_t)NB * NH * LEN * LEN];  // (b,h,q,k) unnormalized E
__device__ float g_L [(size_t)NB * NH * LEN];        // 1/rowsum per (b,h,q)
// pre-rounded inputs
__device__ float g_Qr[XN];
__device__ float g_Kr[XN];
__device__ float g_Vr[XN];
// pre-rounded AND transposed weights: [n][k]
__device__ float g_WqT[WN];
__device__ float g_WkT[WN];
__device__ float g_WvT[WN];
__device__ float g_WoT[WN];

// ---------------- helpers ----------------------------------------------------
__device__ __forceinline__ uint32_t f2tf(float x) {
    uint32_t u;
    asm("cvt.rna.tf32.f32 %0, %1;" : "=r"(u) : "f"(x));
    return u;
}
__device__ __forceinline__ float f2tff(float x) { return __uint_as_float(f2tf(x)); }
__device__ __forceinline__ void mma8(float* d, const uint32_t* a, const uint32_t* b) {
    asm("mma.sync.aligned.m16n8k8.row.col.f32.tf32.tf32.f32 "
        "{%0,%1,%2,%3},{%4,%5,%6,%7},{%8,%9},{%0,%1,%2,%3};"
        : "+f"(d[0]), "+f"(d[1]), "+f"(d[2]), "+f"(d[3])
        : "r"(a[0]), "r"(a[1]), "r"(a[2]), "r"(a[3]), "r"(b[0]), "r"(b[1]));
}
__device__ __forceinline__ void cp16(float* dst, const float* src) {
    uint32_t d = (uint32_t)__cvta_generic_to_shared(dst);
    asm volatile("cp.async.cg.shared.global [%0], [%1], 16;" :: "r"(d), "l"(src));
}
#define CP_COMMIT asm volatile("cp.async.commit_group;")
#define CP_WAIT0  asm volatile("cp.async.wait_group 0;")
#define CP_WAIT1  asm volatile("cp.async.wait_group 1;")
#define LU(p)  __float_as_uint(p)
#define LDSM4(R, addr) \
    asm volatile("ldmatrix.sync.aligned.m8n8.x4.shared.b16 {%0,%1,%2,%3}, [%4];" \
        : "=r"((R)[0]), "=r"((R)[1]), "=r"((R)[2]), "=r"((R)[3]) : "r"(addr))

// ---------------- round q/k/v inputs to tf32 once ----------------------------
__global__ __launch_bounds__(256) void round_kernel(
    const float* __restrict__ q, const float* __restrict__ k,
    const float* __restrict__ v)
{
    const float* src; float* dst;
    switch (blockIdx.z) {
        case 0: src = q; dst = g_Qr; break;
        case 1: src = k; dst = g_Kr; break;
        default: src = v; dst = g_Vr; break;
    }
    size_t stride = (size_t)gridDim.x * blockDim.x;
    for (size_t i = (size_t)blockIdx.x * blockDim.x + threadIdx.x; i < XN / 4; i += stride) {
        float4 t = ((const float4*)src)[i];
        t.x = f2tff(t.x); t.y = f2tff(t.y); t.z = f2tff(t.z); t.w = f2tff(t.w);
        ((float4*)dst)[i] = t;
    }
}

// ---------------- round + transpose weights: W[k][n] -> WT[n][k] -------------
__global__ __launch_bounds__(256) void wtrans_kernel(
    const float* __restrict__ Wq, const float* __restrict__ Wk,
    const float* __restrict__ Wv, const float* __restrict__ Wo)
{
    const float* src; float* dst;
    switch (blockIdx.z) {
        case 0: src = Wq; dst = g_WqT; break;
        case 1: src = Wk; dst = g_WkT; break;
        case 2: src = Wv; dst = g_WvT; break;
        default: src = Wo; dst = g_WoT; break;
    }
    __shared__ float tile[32][33];
    int tx = threadIdx.x & 31, ty = threadIdx.x >> 5;  // 32 x 8
    int k0 = blockIdx.y * 32, n0 = blockIdx.x * 32;
    #pragma unroll
    for (int j = 0; j < 4; j++)
        tile[ty + 8 * j][tx] = src[(size_t)(k0 + ty + 8 * j) * 1024 + n0 + tx];
    __syncthreads();
    #pragma unroll
    for (int j = 0; j < 4; j++)
        dst[(size_t)(n0 + ty + 8 * j) * 1024 + k0 + tx] = f2tff(tile[tx][ty + 8 * j]);
}

// ---------------- GEMM core (tf32 mma + ldmatrix, 128x128, 2-stage) ----------
// A: X[m][k] row-major tile As[128][36]; B: WT[n][k] tile Bs[128][36].
#define GA   (128 * 36)
#define GBT  (128 * 36)
#define GSTG (GA + GBT)              // floats per stage
#define GEMM_SMEM (2 * GSTG * 4)     // 73728 B -> 2 CTAs/SM

__device__ __forceinline__ void gemm_copy_tile(
    float* As, float* Bs, const float* X, const float* WT,
    int row0, int n0, int k0, int tid)
{
    #pragma unroll
    for (int p = 0; p < 4; p++) {
        int idx = p * 256 + tid;
        int m = idx >> 3, kf = idx & 7;
        cp16(&As[m * 36 + 4 * kf], &X[(size_t)(row0 + m) * 1024 + k0 + 4 * kf]);
    }
    #pragma unroll
    for (int p = 0; p < 4; p++) {
        int idx = p * 256 + tid;
        int n = idx >> 3, kf = idx & 7;
        cp16(&Bs[n * 36 + 4 * kf], &WT[(size_t)(n0 + n) * 1024 + k0 + 4 * kf]);
    }
    CP_COMMIT;
}

__device__ __forceinline__ void gemm_core(
    const float* X, const float* WT, float d[2][8][4],
    int row0, int n0, int tid, float* smx)
{
    int lane = tid & 31, wrp = tid >> 5;
    int mw = (wrp & 3) * 32;        // 4 warps along M
    int nw = (wrp >> 2) * 64;       // 2 warps along N (64 each)

    uint32_t smem_u = (uint32_t)__cvta_generic_to_shared(smx);
    // A fragments: rows mw+(lane&15), col-half lane>>4
    uint32_t aB = smem_u + 4u * ((mw + (lane & 15)) * 36 + (lane >> 4) * 4);
    // B fragments: rows nw + i*16 + (lane&7) + 8*(lane>>4), half (lane>>3)&1
    uint32_t bB[4];
    #pragma unroll
    for (int i = 0; i < 4; i++)
        bB[i] = smem_u + 4u * GA +
                4u * ((nw + i * 16 + (lane & 7) + ((lane >> 4) & 1) * 8) * 36 +
                      ((lane >> 3) & 1) * 4);
    const uint32_t STGB = GSTG * 4;  // stage stride bytes

    gemm_copy_tile(smx, smx + GA, X, WT, row0, n0, 0, tid);

    #pragma unroll 1
    for (int t = 0; t < 32; t++) {
        uint32_t soff = (t & 1) ? STGB : 0;
        float* nAs = smx + ((t + 1) & 1) * GSTG;
        CP_WAIT0;
        __syncthreads();
        if (t < 31) gemm_copy_tile(nAs, nAs + GA, X, WT, row0, n0, (t + 1) * 32, tid);

        #pragma unroll
        for (int ks = 0; ks < 4; ks++) {
            uint32_t a0[4], a1[4], b0[4], b1[4], b2[4], b3[4];
            LDSM4(a0, aB + soff + ks * 32);
            LDSM4(a1, aB + soff + ks * 32 + 16u * 36 * 4);
            LDSM4(b0, bB[0] + soff + ks * 32);
            LDSM4(b1, bB[1] + soff + ks * 32);
            LDSM4(b2, bB[2] + soff + ks * 32);
            LDSM4(b3, bB[3] + soff + ks * 32);
            mma8(d[0][0], a0, b0);     mma8(d[1][0], a1, b0);
            mma8(d[0][1], a0, b0 + 2); mma8(d[1][1], a1, b0 + 2);
            mma8(d[0][2], a0, b1);     mma8(d[1][2], a1, b1);
            mma8(d[0][3], a0, b1 + 2); mma8(d[1][3], a1, b1 + 2);
            mma8(d[0][4], a0, b2);     mma8(d[1][4], a1, b2);
            mma8(d[0][5], a0, b2 + 2); mma8(d[1][5], a1, b2 + 2);
            mma8(d[0][6], a0, b3);     mma8(d[1][6], a1, b3);
            mma8(d[0][7], a0, b3 + 2); mma8(d[1][7], a1, b3 + 2);
        }
    }
}

// ---------------- projection kernel ------------------------------------------
__global__ __launch_bounds__(256, 2) void proj_kernel(
    const float* __restrict__ bq, const float* __restrict__ bk,
    const float* __restrict__ bv)
{
    extern __shared__ float smx[];
    const float* X; const float* WT; const float* bias; float* out;
    int z = blockIdx.z;
    if (z == 0)      { X = g_Qr; WT = g_WqT; bias = bq; out = g_Qp; }
    else if (z == 1) { X = g_Kr; WT = g_WkT; bias = bk; out = g_Kp; }
    else             { X = g_Vr; WT = g_WvT; bias = bv; out = g_Vp; }
    bool vtrans = (z == 2);

    int tid = threadIdx.x;
    int lane = tid & 31, wrp = tid >> 5;
    int lr = lane >> 2, lc = lane & 3;
    int mw = (wrp & 3) * 32, nw = (wrp >> 2) * 64;
    int row0 = blockIdx.y * 128;
    int n0   = blockIdx.x * 128;

    float d[2][8][4];
    #pragma unroll
    for (int mt = 0; mt < 2; mt++)
        #pragma unroll
        for (int nt = 0; nt < 8; nt++)
            #pragma unroll
            for (int r = 0; r < 4; r++) d[mt][nt][r] = 0.f;

    gemm_core(X, WT, d, row0, n0, tid, smx);

    // epilogue: head-major scatter, tf32-rounded. e = x*16 + h
    #pragma unroll
    for (int mt = 0; mt < 2; mt++)
        #pragma unroll
        for (int nt = 0; nt < 8; nt++)
            #pragma unroll
            for (int r = 0; r < 4; r++) {
                int row = row0 + mw + mt * 16 + lr + ((r >= 2) ? 8 : 0);
                int e = n0 + nw + nt * 8 + 2 * lc + (r & 1);
                int b = row >> 11, l = row & 2047;
                int hh = e & 15, x = e >> 4;
                float v = f2tff(d[mt][nt][r] + bias[e]);
                if (vtrans)
                    out[(((size_t)(b * 16 + hh) * HX) + x) * LEN + l] = v;
                else
                    out[(((size_t)(b * 16 + hh) * LEN) + l) * HX + x] = v;
            }
}

// ---------------- output projection kernel -----------------------------------
__global__ __launch_bounds__(256, 2) void outproj_kernel(
    const float* __restrict__ bo, float* __restrict__ out)
{
    extern __shared__ float smx[];
    int tid = threadIdx.x;
    int lane = tid & 31, wrp = tid >> 5;
    int lr = lane >> 2, lc = lane & 3;
    int mw = (wrp & 3) * 32, nw = (wrp >> 2) * 64;
    int row0 = blockIdx.y * 128;
    int n0   = blockIdx.x * 128;

    float d[2][8][4];
    #pragma unroll
    for (int mt = 0; mt < 2; mt++)
        #pragma unroll
        for (int nt = 0; nt < 8; nt++)
            #pragma unroll
            for (int r = 0; r < 4; r++) d[mt][nt][r] = 0.f;

    gemm_core(g_AO, g_WoT, d, row0, n0, tid, smx);

    #pragma unroll
    for (int mt = 0; mt < 2; mt++)
        #pragma unroll
        for (int nt = 0; nt < 8; nt++)
            #pragma unroll
            for (int r = 0; r < 4; r++) {
                size_t row = row0 + mw + mt * 16 + lr + ((r >= 2) ? 8 : 0);
                int e = n0 + nw + nt * 8 + 2 * lc + (r & 1);
                out[row * 1024 + e] = d[mt][nt][r] + bo[e];
            }
}

// ---------------- attention kernel (R10-exact: double-K, 5 buffers) ----------
#define SST 68
#define ATT (64 * SST)
#define ATT_SMEM (5 * ATT * 4)   // 87040 B -> 2 CTAs/SM

__global__ __launch_bounds__(256, 2) void attn_kernel(const unsigned char* __restrict__ mask)
{
    extern __shared__ float sm[];
    float* Qs  = sm;               // [q][x]
    float* Ks0 = sm + ATT;         // [k][x]
    float* Ks1 = sm + 2 * ATT;
    float* Vs  = sm + 3 * ATT;     // [x][k]
    float* Ss  = sm + 4 * ATT;     // [q][k] E (tf32-rounded)
    __shared__ float lrow[64];

    int tid = threadIdx.x;
    int lane = tid & 31, wrp = tid >> 5;
    int lr = lane >> 2, lc = lane & 3;
    int kw = (wrp >> 1) * 16;      // warp k-rows (QK) / x-rows (PV)
    int qw = (wrp & 1) * 32;       // warp q-cols
    int q0 = blockIdx.x * 64;
    int h  = blockIdx.y;
    int b  = blockIdx.z;
    size_t bh = (size_t)(b * 16 + h);

    const float* Qbase = g_Qp + bh * LEN * HX + (size_t)q0 * HX;
    const float* Kb    = g_Kp + bh * LEN * HX;
    const float* VbT   = g_Vp + bh * HX * LEN;          // [x][k]
    float*       Pb    = g_P  + bh * LEN * LEN + (size_t)q0 * LEN;
    const unsigned char* maskb = mask + b * LEN;

    // ldmatrix per-thread base addresses (bytes)
    uint32_t qs_u = (uint32_t)__cvta_generic_to_shared(Qs);
    uint32_t k0_u = (uint32_t)__cvta_generic_to_shared(Ks0);
    uint32_t k1_u = (uint32_t)__cvta_generic_to_shared(Ks1);
    uint32_t vs_u = (uint32_t)__cvta_generic_to_shared(Vs);
    uint32_t ss_u = (uint32_t)__cvta_generic_to_shared(Ss);
    uint32_t aoff = 4u * ((kw + (lane & 15)) * SST + (lane >> 4) * 4);
    uint32_t ksB0 = k0_u + aoff;
    uint32_t ksB1 = k1_u + aoff;
    uint32_t vsB  = vs_u + aoff;
    uint32_t boff = 4u * ((qw + (lane & 7) + (lane >> 4) * 8) * SST + ((lane >> 3) & 1) * 4);
    uint32_t qsB0 = qs_u + boff;
    uint32_t qsB1 = qsB0 + 4u * 16 * SST;
    uint32_t ssB0 = ss_u + boff;
    uint32_t ssB1 = ssB0 + 4u * 16 * SST;

    // running P pointers, one per nt (advance 64 floats/tile)
    float* pptr[4];
    #pragma unroll
    for (int nt = 0; nt < 4; nt++)
        pptr[nt] = Pb + (size_t)(qw + nt * 8 + 2 * lc) * LEN + kw + lr;

    // prologue: async-copy Q tile + K tile 0 (one group)
    #pragma unroll
    for (int p = 0; p < 4; p++) {
        int idx = p * 256 + tid;
        int r = idx >> 4, f = idx & 15;
        cp16(&Qs[r * SST + 4 * f], &Qbase[idx * 4]);
        cp16(&Ks0[r * SST + 4 * f], &Kb[idx * 4]);
    }
    CP_COMMIT;
    if (tid < 64) lrow[tid] = 0.f;

    float ofr[4][4];
    float cs[4][2];
    #pragma unroll
    for (int nt = 0; nt < 4; nt++) {
        cs[nt][0] = 0.f; cs[nt][1] = 0.f;
        #pragma unroll
        for (int r = 0; r < 4; r++) ofr[nt][r] = 0.f;
    }

    #pragma unroll 1
    for (int kt = 0; kt < 32; kt++) {
        int k0 = kt * 64;
        uint32_t ksB = (kt & 1) ? ksB1 : ksB0;
        float* Ksn   = (kt & 1) ? Ks0 : Ks1;
        CP_WAIT0;            // K(kt) (and Q on kt=0) ready
        __syncthreads();     // all warps done with PV(kt-1) -> Vs reusable

        // issue V(kt) copy (own group), then K(kt+1)
        #pragma unroll
        for (int p = 0; p < 4; p++) {
            int idx = p * 256 + tid;
            int x = idx >> 4, f = idx & 15;
            cp16(&Vs[x * SST + 4 * f], &VbT[(size_t)x * LEN + k0 + 4 * f]);
        }
        CP_COMMIT;
        if (kt < 31) {
            #pragma unroll
            for (int p = 0; p < 4; p++) {
                int idx = p * 256 + tid;
                int r = idx >> 4, f = idx & 15;
                cp16(&Ksn[r * SST + 4 * f], &Kb[(size_t)(k0 + 64) * HX + idx * 4]);
            }
            CP_COMMIT;
        }

        float mk_lo = (float)maskb[k0 + kw + lr];
        float mk_hi = (float)maskb[k0 + kw + lr + 8];

        // S^T = K @ Q^T via ldmatrix fragments
        float sfr[4][4];
        #pragma unroll
        for (int nt = 0; nt < 4; nt++)
            #pragma unroll
            for (int r = 0; r < 4; r++) sfr[nt][r] = 0.f;
        #pragma unroll
        for (int xs = 0; xs < 8; xs++) {
            uint32_t aK[4], b01[4], b23[4];
            LDSM4(aK, ksB + xs * 32);
            LDSM4(b01, qsB0 + xs * 32);
            LDSM4(b23, qsB1 + xs * 32);
            mma8(sfr[0], aK, b01);
            mma8(sfr[1], aK, b01 + 2);
            mma8(sfr[2], aK, b23);
            mma8(sfr[3], aK, b23 + 2);
        }

        // E = exp(S/T) (masked -> 0); csum in regs; P direct from registers;
        // Ss[q][k] gets tf32-rounded values for the PV ldmatrix.
        #pragma unroll
        for (int nt = 0; nt < 4; nt++) {
            int qb = qw + nt * 8 + 2 * lc;
            float e00 = (mk_lo != 0.f) ? 0.f : __expf(sfr[nt][0] * TEMPINV);
            float e01 = (mk_lo != 0.f) ? 0.f : __expf(sfr[nt][1] * TEMPINV);
            float e10 = (mk_hi != 0.f) ? 0.f : __expf(sfr[nt][2] * TEMPINV);
            float e11 = (mk_hi != 0.f) ? 0.f : __expf(sfr[nt][3] * TEMPINV);
            cs[nt][0] += e00 + e10;
            cs[nt][1] += e01 + e11;
            float* p = pptr[nt];
            p[0]       = e00;
            p[LEN]     = e01;
            p[8]       = e10;
            p[LEN + 8] = e11;
            pptr[nt] = p + 64;
            Ss[(qb    ) * SST + kw + lr    ] = f2tff(e00);
            Ss[(qb    ) * SST + kw + lr + 8] = f2tff(e10);
            Ss[(qb + 1) * SST + kw + lr    ] = f2tff(e01);
            Ss[(qb + 1) * SST + kw + lr + 8] = f2tff(e11);
        }
        // V(kt) must be resident before PV; K(kt+1) may still be in flight
        if (kt < 31) { CP_WAIT1; } else { CP_WAIT0; }
        __syncthreads();

        // PV: O^T += V^T @ E^T via ldmatrix
        #pragma unroll
        for (int ks = 0; ks < 8; ks++) {
            uint32_t aV[4], b01[4], b23[4];
            LDSM4(aV, vsB + ks * 32);
            LDSM4(b01, ssB0 + ks * 32);
            LDSM4(b23, ssB1 + ks * 32);
            mma8(ofr[0], aV, b01);
            mma8(ofr[1], aV, b01 + 2);
            mma8(ofr[2], aV, b23);
            mma8(ofr[3], aV, b23 + 2);
        }
    }

    // reduce csum: over lr (shfl), then across warps (shared atomics)
    #pragma unroll
    for (int nt = 0; nt < 4; nt++)
        #pragma unroll
        for (int j = 0; j < 2; j++) {
            float s = cs[nt][j];
            s += __shfl_xor_sync(0xffffffffu, s, 4);
            s += __shfl_xor_sync(0xffffffffu, s, 8);
            s += __shfl_xor_sync(0xffffffffu, s, 16);
            if (lane < 4) atomicAdd(&lrow[qw + nt * 8 + 2 * lc + j], s);
        }
    __syncthreads();
    if (tid < 64) {
        float inv = 1.f / lrow[tid];
        lrow[tid] = inv;
        g_L[bh * LEN + q0 + tid] = inv;
    }
    __syncthreads();

    // write O scaled by 1/l, tf32-rounded (outproj consumes without CVT)
    int xw = kw;
    #pragma unroll
    for (int nt = 0; nt < 4; nt++) {
        int ql = qw + nt * 8 + 2 * lc;
        int qg = q0 + ql;
        int x0 = xw + lr;
        float l0 = lrow[ql], l1 = lrow[ql + 1];
        g_AO[((size_t)b * LEN + qg    ) * EMB + x0 * 16 + h]       = f2tff(ofr[nt][0] * l0);
        g_AO[((size_t)b * LEN + qg + 1) * EMB + x0 * 16 + h]       = f2tff(ofr[nt][1] * l1);
        g_AO[((size_t)b * LEN + qg    ) * EMB + (x0 + 8) * 16 + h] = f2tff(ofr[nt][2] * l0);
        g_AO[((size_t)b * LEN + qg + 1) * EMB + (x0 + 8) * 16 + h] = f2tff(ofr[nt][3] * l1);
    }
}

// ---------------- transpose+normalize: (b,h,q,k) E -> out2 (b,q,k,h) P -------
__global__ __launch_bounds__(256) void transpose_kernel(float* __restrict__ out2)
{
    __shared__ float tile[16 * 257];
    __shared__ float linv16[16];
    int tid = threadIdx.x;
    int b = blockIdx.z, q = blockIdx.y, k0 = blockIdx.x * 256;

    if (tid < 16) linv16[tid] = g_L[((size_t)(b * 16 + tid)) * LEN + q];

    const float* src = g_P + ((size_t)(b * 16) * LEN + q) * LEN + k0;
    #pragma unroll
    for (int hh = 0; hh < 16; hh++)
        tile[hh * 257 + tid] = src[(size_t)hh * LEN * LEN + tid];
    __syncthreads();

    float* dst = out2 + ((size_t)(b * LEN + q) * LEN + k0 + tid) * 16;
    #pragma unroll
    for (int g = 0; g < 4; g++) {
        float4 v;
        v.x = tile[(4 * g + 0) * 257 + tid] * linv16[4 * g + 0];
        v.y = tile[(4 * g + 1) * 257 + tid] * linv16[4 * g + 1];
        v.z = tile[(4 * g + 2) * 257 + tid] * linv16[4 * g + 2];
        v.w = tile[(4 * g + 3) * 257 + tid] * linv16[4 * g + 3];
        *(float4*)&dst[4 * g] = v;
    }
}

// ---------------- launch -----------------------------------------------------
extern "C" void kernel_launch(void* const* d_in, const int* in_sizes, int n_in,
                              void* d_out, int out_size)
{
    const float* query = (const float*)d_in[0];
    const float* key   = (const float*)d_in[1];
    const float* value = (const float*)d_in[2];
    const unsigned char* mask = (const unsigned char*)d_in[3];
    const float* bq = (const float*)d_in[5];
    const float* bk = (const float*)d_in[7];
    const float* bv = (const float*)d_in[9];
    const float* bo = (const float*)d_in[11];
    const float* Wq = (const float*)d_in[4];
    const float* Wk = (const float*)d_in[6];
    const float* Wv = (const float*)d_in[8];
    const float* Wo = (const float*)d_in[10];
    float* out = (float*)d_out;

    cudaFuncSetAttribute(attn_kernel, cudaFuncAttributeMaxDynamicSharedMemorySize, ATT_SMEM);
    cudaFuncSetAttribute(proj_kernel, cudaFuncAttributeMaxDynamicSharedMemorySize, GEMM_SMEM);
    cudaFuncSetAttribute(outproj_kernel, cudaFuncAttributeMaxDynamicSharedMemorySize, GEMM_SMEM);

    round_kernel<<<dim3(192, 1, 3), 256>>>(query, key, value);
    wtrans_kernel<<<dim3(32, 32, 4), 256>>>(Wq, Wk, Wv, Wo);
    proj_kernel<<<dim3(8, 32, 3), 256, GEMM_SMEM>>>(bq, bk, bv);
    attn_kernel<<<dim3(LEN / 64, NH, NB), 256, ATT_SMEM>>>(mask);
    transpose_kernel<<<dim3(LEN / 256, LEN, NB), 256>>>(out + (size_t)NB * LEN * EMB);
    outproj_kernel<<<dim3(8, 32), 256, GEMM_SMEM>>>(bo, out);
}